// round 16
// baseline (speedup 1.0000x reference)
#include <cuda_runtime.h>
#include <cuda_bf16.h>
#include <math.h>
#include <stdint.h>

// ---------------- problem constants ----------------
#define BATCH 2
#define SEQ   2048
#define HID   2048
#define NH    16
#define DQK   192
#define DV    128
#define QLORA 1536
#define KVLORA 512
#define ROPE_D 64
#define TOK   (BATCH*SEQ)          // 4096
#define BHN   (BATCH*NH)           // 32
#define QKVD  (QLORA + KVLORA + ROPE_D)   // 2112

// ---------------- fp32 scratch ----------------
__device__ float g_qc  [(size_t)TOK * QKVD];
__device__ float g_q1n [(size_t)TOK * QLORA];
__device__ float g_q   [(size_t)TOK * (NH*DQK)];
__device__ float g_ckn [(size_t)TOK * KVLORA];
__device__ float g_kv  [(size_t)TOK * (NH*256)];
__device__ float g_qbuf[(size_t)BHN * SEQ * DQK];
__device__ float g_kbuf[(size_t)BHN * SEQ * DQK];
__device__ float g_vt  [(size_t)BHN * DV * SEQ];
__device__ float g_om  [(size_t)TOK * (NH*DV)];
__device__ float g_attn[(size_t)BHN * SEQ * SEQ];
__device__ float g_invf[32];
__device__ float g_hsr [(size_t)TOK*HID];
__device__ float g_wqkd[(size_t)QKVD*HID];
__device__ float g_wqu [(size_t)(NH*DQK)*QLORA];
__device__ float g_wku [(size_t)(NH*256)*KVLORA];
__device__ float g_wo  [(size_t)HID*(NH*DV)];

// ================= helpers =================
__device__ __forceinline__ uint32_t smem_u32(const void* p) {
    uint32_t a;
    asm("{ .reg .u64 t; cvta.to.shared.u64 t, %1; cvt.u32.u64 %0, t; }" : "=r"(a) : "l"(p));
    return a;
}
__device__ __forceinline__ float rna_tf32(float x) {
    uint32_t t; asm("cvt.rna.tf32.f32 %0, %1;" : "=r"(t) : "f"(x));
    return __uint_as_float(t);
}
__device__ __forceinline__ void mma_tf32(float* d, const uint32_t* a, const uint32_t* b) {
    asm volatile("mma.sync.aligned.m16n8k8.row.col.f32.tf32.tf32.f32 "
        "{%0,%1,%2,%3}, {%4,%5,%6,%7}, {%8,%9}, {%0,%1,%2,%3};"
        : "+f"(d[0]), "+f"(d[1]), "+f"(d[2]), "+f"(d[3])
        : "r"(a[0]), "r"(a[1]), "r"(a[2]), "r"(a[3]), "r"(b[0]), "r"(b[1]));
}
__device__ __forceinline__ void cp16(uint32_t dst, const void* src, bool v) {
    int sz = v ? 16 : 0;
    asm volatile("cp.async.cg.shared.global [%0], [%1], 16, %2;"
        :: "r"(dst), "l"(src), "r"(sz) : "memory");
}
#define CP_COMMIT() asm volatile("cp.async.commit_group;" ::: "memory")
#define CP_WAIT(n)  asm volatile("cp.async.wait_group %0;" :: "n"(n) : "memory")

// ---------------- batched single-pass TF32 tensor GEMM --------------------
// 128x128 block, 4 warps (2x2), warp tile 64x64, cp.async 3-stage.
// C = alpha * A * B^T ; mode 0 plain; 1 causal (skip+zero-fill); 2 K clamp.
#define TSTRF 36
#define BUFF (128*TSTRF*4)
#define STGF (2*BUFF)
#define SMEMF (3*STGF)

__global__ __launch_bounds__(128, 2) void mma_gemm(
    const float* __restrict__ A, const float* __restrict__ B,
    float* __restrict__ C,
    long lda, long sA, long ldb, long sB,
    long ldc, long sC, long sC2, int zdiv,
    int M, int N, int K, float alpha, int mode, int rndC)
{
    extern __shared__ char dsm[];
    const uint32_t sb = smem_u32(dsm);

    const int z = blockIdx.z;
    float* Cb = C + (size_t)(z / zdiv) * sC + (size_t)(z % zdiv) * sC2;

    const int tid = threadIdx.x;
    const int m0 = blockIdx.y * 128, n0 = blockIdx.x * 128;

    if (mode == 1 && n0 >= m0 + 128) {
        const float4 z4 = make_float4(0.f, 0.f, 0.f, 0.f);
#pragma unroll
        for (int i = 0; i < 32; i++) {
            int idx = i * 128 + tid;           // 4096 float4 slots
            int row = idx >> 5, col = (idx & 31) * 4;
            *(float4*)&Cb[(size_t)(m0 + row) * ldc + n0 + col] = z4;
        }
        return;
    }

    const float* Ab = A + (size_t)z * sA;
    const float* Bb = B + (size_t)z * sB;

    const int lane = tid & 31;
    const int wid = tid >> 5;          // 0..3
    const int wm = wid >> 1;           // 0..1 -> 64 rows
    const int wn = wid & 1;            // 0..1 -> 64 cols
    int Keff = (mode == 2) ? min(K, m0 + 128) : K;
    const int nk = Keff / 32;

    float acc[4][8][4];
#pragma unroll
    for (int i = 0; i < 4; i++)
#pragma unroll
        for (int j = 0; j < 8; j++)
#pragma unroll
            for (int f = 0; f < 4; f++) acc[i][j][f] = 0.f;

    const int la = lane >> 2, lc = lane & 3;
    const int boff = (wn * 64 + la) * TSTRF + lc;
    const int aoff = (wm * 64 + la) * TSTRF + lc;

    auto issue = [&](int s, int k0) {
        const uint32_t base = sb + s * STGF;
#pragma unroll
        for (int j = 0; j < 8; j++) {
            int ci = tid + 128 * j;            // 0..1023
            int row = ci >> 3, col = (ci & 7) * 4;
            uint32_t so = (uint32_t)(row * TSTRF + col) * 4;
            cp16(base + so, Ab + (size_t)(m0 + row) * lda + k0 + col, true);
            bool v = (n0 + row) < N;
            const float* bs = Bb + (size_t)(v ? (n0 + row) : 0) * ldb + k0 + col;
            cp16(base + BUFF + so, bs, v);
        }
    };

    issue(0, 0);
    CP_COMMIT();
    if (nk > 1) { issue(1, 32); CP_COMMIT(); }

    for (int it = 0; it < nk; it++) {
        if (it + 2 < nk) {
            issue((it + 2) % 3, (it + 2) * 32);
            CP_COMMIT();
            CP_WAIT(2);
        } else if (it + 1 < nk) {
            CP_WAIT(1);
        } else {
            CP_WAIT(0);
        }
        __syncthreads();

        const float* As = (const float*)(dsm + (it % 3) * STGF);
        const float* Bs = (const float*)(dsm + (it % 3) * STGF + BUFF);

#pragma unroll
        for (int k8 = 0; k8 < 4; k8++) {
            const int kc = k8 * 8;
            uint32_t bf[8][2];
#pragma unroll
            for (int nj = 0; nj < 8; nj++) {
                const float* bp = Bs + boff + nj * 8 * TSTRF + kc;
                bf[nj][0] = __float_as_uint(bp[0]);
                bf[nj][1] = __float_as_uint(bp[4]);
            }
#pragma unroll
            for (int mi = 0; mi < 4; mi++) {
                const float* ap = As + aoff + mi * 16 * TSTRF + kc;
                uint32_t af[4];
                af[0] = __float_as_uint(ap[0]);
                af[1] = __float_as_uint(ap[8 * TSTRF]);
                af[2] = __float_as_uint(ap[4]);
                af[3] = __float_as_uint(ap[8 * TSTRF + 4]);
#pragma unroll
                for (int nj = 0; nj < 8; nj++)
                    mma_tf32(acc[mi][nj], af, bf[nj]);
            }
        }
        __syncthreads();
    }

#pragma unroll
    for (int mi = 0; mi < 4; mi++) {
        const int m1 = m0 + wm * 64 + mi * 16 + la;
        const int m2 = m1 + 8;
#pragma unroll
        for (int nj = 0; nj < 8; nj++) {
            const int n = n0 + wn * 64 + nj * 8 + lc * 2;
            if (n < N) {
                float v0 = alpha * acc[mi][nj][0], v1 = alpha * acc[mi][nj][1];
                float v2 = alpha * acc[mi][nj][2], v3 = alpha * acc[mi][nj][3];
                if (rndC) { v0 = rna_tf32(v0); v1 = rna_tf32(v1); v2 = rna_tf32(v2); v3 = rna_tf32(v3); }
                *(float2*)&Cb[(size_t)m1 * ldc + n] = make_float2(v0, v1);
                *(float2*)&Cb[(size_t)m2 * ldc + n] = make_float2(v2, v3);
            }
        }
    }
}

// ---------------- vectorized tf32 pre-round ----------------
__global__ __launch_bounds__(256) void round4(
    const float4* __restrict__ x, float4* __restrict__ o, long n4)
{
    long i = (long)blockIdx.x * 256 + threadIdx.x;
    if (i >= n4) return;
    float4 v = x[i];
    v.x = rna_tf32(v.x); v.y = rna_tf32(v.y);
    v.z = rna_tf32(v.z); v.w = rna_tf32(v.w);
    o[i] = v;
}

// ---------------- RMSNorm with tf32-rounded output ----------------
__global__ __launch_bounds__(256) void rmsnorm_round(
    const float* __restrict__ in, long ldin,
    const float* __restrict__ w,
    float* __restrict__ out, long ldout, int D)
{
    const int row = blockIdx.x;
    const float* x = in + (size_t)row * ldin;
    float* o = out + (size_t)row * ldout;

    float s = 0.f;
    for (int i = threadIdx.x; i < D; i += 256) { float v = x[i]; s += v * v; }
    __shared__ float red[8];
#pragma unroll
    for (int off = 16; off; off >>= 1) s += __shfl_xor_sync(0xffffffffu, s, off);
    if ((threadIdx.x & 31) == 0) red[threadIdx.x >> 5] = s;
    __syncthreads();
    float tot = red[0]+red[1]+red[2]+red[3]+red[4]+red[5]+red[6]+red[7];
    const float inv = rsqrtf(tot / (float)D + 1e-6f);
    for (int i = threadIdx.x; i < D; i += 256) o[i] = rna_tf32(w[i] * x[i] * inv);
}

// ---------------- RoPE table ----------------
__global__ void init_rope() {
    int j = threadIdx.x;
    if (j < 32)
        g_invf[j] = (float)exp(-((double)(2 * j) / 64.0) * log(10000.0));
}

// ---------------- fused RoPE pack ----------------
__global__ __launch_bounds__(256) void rope_pack() {
    const int blk = blockIdx.x;
    const int s  = blk % SEQ;
    const int bh = blk / SEQ;
    const int h = bh % NH, b = bh / NH;
    const long t = (long)b * SEQ + s;
    const int tid = threadIdx.x;

    float* qdst = g_qbuf + (size_t)blk * DQK;
    float* kdst = g_kbuf + (size_t)blk * DQK;
    const float* qsrc  = g_q  + t * (NH * DQK) + (long)h * DQK;
    const float* knsrc = g_kv + t * (NH * 256) + (long)h * 256;
    const float* krsrc = g_qc + t * QKVD + QLORA + KVLORA;

    if (tid < 128) {
        qdst[tid] = rna_tf32(qsrc[tid]);
        kdst[tid] = rna_tf32(knsrc[tid]);
    } else if (tid < 160) {
        int jj = tid - 128;
        float ang = (float)s * g_invf[jj];
        float c = (float)cos((double)ang);
        float sn = (float)sin((double)ang);
        float x0 = qsrc[128 + 2 * jj];
        float x1 = qsrc[128 + 2 * jj + 1];
        qdst[128 + jj] = rna_tf32(x0 * c - x1 * sn);
        qdst[160 + jj] = rna_tf32(x1 * c + x0 * sn);
    } else if (tid < 192) {
        int jj = tid - 160;
        float ang = (float)s * g_invf[jj];
        float c = (float)cos((double)ang);
        float sn = (float)sin((double)ang);
        float x0 = krsrc[2 * jj];
        float x1 = krsrc[2 * jj + 1];
        kdst[128 + jj] = rna_tf32(x0 * c - x1 * sn);
        kdst[160 + jj] = rna_tf32(x1 * c + x0 * sn);
    }
}

// ---------------- V transpose ----------------
__global__ __launch_bounds__(256) void vtrans() {
    long idx = (long)blockIdx.x * 256 + threadIdx.x;
    const long total = (long)BHN * DV * SEQ;
    if (idx >= total) return;
    int s = (int)(idx % SEQ);
    long r = idx / SEQ;
    int d = (int)(r % DV);
    int bh = (int)(r / DV);
    int h = bh % NH, b = bh / NH;
    g_vt[idx] = rna_tf32(g_kv[((size_t)b * SEQ + s) * (NH * 256) + (long)h * 256 + 128 + d]);
}

// ---------------- causal softmax ----------------
__global__ __launch_bounds__(256) void softmax_causal(float* __restrict__ attn) {
    const long r = blockIdx.x;
    const int q = (int)(r % SEQ);
    float* row = attn + r * SEQ;
    const int L = q + 1;
    const int Lc = (L + 127) & ~127;
    const int L4 = L & ~3;

    __shared__ float sh[SEQ];
    __shared__ float red[8];

    float mx = -3.4e38f;
    for (int k = threadIdx.x * 4; k < L4; k += 1024) {
        float4 v = *(const float4*)&row[k];
        *(float4*)&sh[k] = v;
        mx = fmaxf(fmaxf(mx, fmaxf(v.x, v.y)), fmaxf(v.z, v.w));
    }
    for (int k = L4 + threadIdx.x; k < L; k += 256) {
        float v = row[k]; sh[k] = v; mx = fmaxf(mx, v);
    }
#pragma unroll
    for (int o = 16; o; o >>= 1) mx = fmaxf(mx, __shfl_xor_sync(0xffffffffu, mx, o));
    if ((threadIdx.x & 31) == 0) red[threadIdx.x >> 5] = mx;
    __syncthreads();
    mx = fmaxf(fmaxf(fmaxf(red[0], red[1]), fmaxf(red[2], red[3])),
               fmaxf(fmaxf(red[4], red[5]), fmaxf(red[6], red[7])));
    __syncthreads();

    float s = 0.f;
    for (int k = threadIdx.x; k < L; k += 256) {
        float e = expf(sh[k] - mx);
        sh[k] = e;
        s += e;
    }
#pragma unroll
    for (int o = 16; o; o >>= 1) s += __shfl_xor_sync(0xffffffffu, s, o);
    if ((threadIdx.x & 31) == 0) red[threadIdx.x >> 5] = s;
    __syncthreads();
    s = red[0]+red[1]+red[2]+red[3]+red[4]+red[5]+red[6]+red[7];
    const float inv = 1.f / s;
    __syncthreads();

    for (int k = threadIdx.x * 4; k < L4; k += 1024) {
        float4 v = *(const float4*)&sh[k];
        v.x = rna_tf32(v.x * inv); v.y = rna_tf32(v.y * inv);
        v.z = rna_tf32(v.z * inv); v.w = rna_tf32(v.w * inv);
        *(float4*)&row[k] = v;
    }
    for (int k = L4 + threadIdx.x; k < L; k += 256)
        row[k] = rna_tf32(sh[k] * inv);
    for (int k = L + threadIdx.x; k < Lc; k += 256)
        row[k] = 0.f;
}

// ---------------- host launch ----------------
static inline int cdiv(long a, long b) { return (int)((a + b - 1) / b); }

extern "C" void kernel_launch(void* const* d_in, const int* in_sizes, int n_in,
                              void* d_out, int out_size)
{
    const float *hs = 0, *w_q_down = 0, *q_norm_w = 0, *w_q_up = 0;
    const float *w_kv_down = 0, *kv_norm_w = 0, *w_kv_up = 0, *w_out = 0;
    for (int i = 0; i < n_in; i++) {
        long n = in_sizes[i];
        const float* ptr = (const float*)d_in[i];
        if (n == 8388608)      { if (!hs) hs = ptr; }
        else if (n == 3145728) w_q_down = ptr;
        else if (n == 1536)    q_norm_w = ptr;
        else if (n == 4718592) w_q_up = ptr;
        else if (n == 1179648) w_kv_down = ptr;
        else if (n == 512)     kv_norm_w = ptr;
        else if (n == 2097152) w_kv_up = ptr;
        else if (n == 4194304) w_out = ptr;
    }

    float* out_final = (float*)d_out;

    void* p;
    cudaGetSymbolAddress(&p, g_qc);   float* qc   = (float*)p;
    cudaGetSymbolAddress(&p, g_q1n);  float* q1n  = (float*)p;
    cudaGetSymbolAddress(&p, g_q);    float* q    = (float*)p;
    cudaGetSymbolAddress(&p, g_ckn);  float* ckn  = (float*)p;
    cudaGetSymbolAddress(&p, g_kv);   float* kv   = (float*)p;
    cudaGetSymbolAddress(&p, g_qbuf); float* qb   = (float*)p;
    cudaGetSymbolAddress(&p, g_kbuf); float* kb   = (float*)p;
    cudaGetSymbolAddress(&p, g_vt);   float* vt   = (float*)p;
    cudaGetSymbolAddress(&p, g_om);   float* om   = (float*)p;
    cudaGetSymbolAddress(&p, g_attn); float* attn_scratch = (float*)p;
    cudaGetSymbolAddress(&p, g_hsr);  float* hsr  = (float*)p;
    cudaGetSymbolAddress(&p, g_wqkd); float* wqkd = (float*)p;
    cudaGetSymbolAddress(&p, g_wqu);  float* wqu  = (float*)p;
    cudaGetSymbolAddress(&p, g_wku);  float* wku  = (float*)p;
    cudaGetSymbolAddress(&p, g_wo);   float* wo   = (float*)p;

    cudaFuncSetAttribute(mma_gemm, cudaFuncAttributeMaxDynamicSharedMemorySize, SMEMF);

    static cudaStream_t s1 = 0, s2 = 0;
    static cudaEvent_t e0 = 0, eW = 0, eDn = 0, eKv = 0, eVt = 0;
    if (!s1) {
        cudaStreamCreateWithFlags(&s1, cudaStreamNonBlocking);
        cudaStreamCreateWithFlags(&s2, cudaStreamNonBlocking);
        cudaEventCreateWithFlags(&e0,  cudaEventDisableTiming);
        cudaEventCreateWithFlags(&eW,  cudaEventDisableTiming);
        cudaEventCreateWithFlags(&eDn, cudaEventDisableTiming);
        cudaEventCreateWithFlags(&eKv, cudaEventDisableTiming);
        cudaEventCreateWithFlags(&eVt, cudaEventDisableTiming);
    }

    const size_t need = (size_t)TOK * HID + (size_t)BHN * SEQ * SEQ;
    float* attn_out = ((size_t)out_size >= need)
                    ? (float*)d_out + (size_t)TOK * HID
                    : attn_scratch;

    const float qk_scale = 1.0f / sqrtf((float)DQK);

    cudaEventRecord(e0, 0);
    cudaStreamWaitEvent(s1, e0, 0);

    // s1: weight rounds not needed by the down GEMM
    { long n4 = (long)(NH*DQK)*QLORA/4; round4<<<cdiv(n4,256),256,0,s1>>>((const float4*)w_q_up, (float4*)wqu, n4); }
    { long n4 = (long)(NH*256)*KVLORA/4; round4<<<cdiv(n4,256),256,0,s1>>>((const float4*)w_kv_up, (float4*)wku, n4); }
    { long n4 = (long)HID*(NH*DV)/4;    round4<<<cdiv(n4,256),256,0,s1>>>((const float4*)w_out, (float4*)wo, n4); }
    cudaEventRecord(eW, s1);

    // s0: inputs needed by down GEMM
    init_rope<<<1, 32>>>();
    { long n4 = (long)TOK*HID/4;              round4<<<cdiv(n4,256),256>>>((const float4*)hs, (float4*)hsr, n4); }
    { long n4 = (long)QLORA*HID/4;            round4<<<cdiv(n4,256),256>>>((const float4*)w_q_down, (float4*)wqkd, n4); }
    { long n4 = (long)(KVLORA+ROPE_D)*HID/4;  round4<<<cdiv(n4,256),256>>>((const float4*)w_kv_down, (float4*)(wqkd + (size_t)QLORA*HID), n4); }

    // down: qc = hs @ concat(wq,wkv)^T
    mma_gemm<<<dim3(cdiv(QKVD,128), TOK/128), 128, SMEMF>>>(
        hsr, wqkd, qc,
        HID, 0, HID, 0, QKVD, 0, 0, 1,
        TOK, QKVD, HID, 1.f, 0, 0);
    cudaEventRecord(eDn, 0);

    // s2: KV path
    cudaStreamWaitEvent(s2, eDn, 0);
    cudaStreamWaitEvent(s2, eW, 0);
    rmsnorm_round<<<TOK, 256, 0, s2>>>(qc + QLORA, QKVD, kv_norm_w, ckn, KVLORA, KVLORA);
    mma_gemm<<<dim3((NH*256)/128, TOK/128), 128, SMEMF, s2>>>(
        ckn, wku, kv,
        KVLORA, 0, KVLORA, 0, NH*256, 0, 0, 1,
        TOK, NH*256, KVLORA, 1.f, 0, 0);
    cudaEventRecord(eKv, s2);
    {
        long total = (long)BHN * DV * SEQ;
        vtrans<<<(int)((total + 255) / 256), 256, 0, s2>>>();
    }
    cudaEventRecord(eVt, s2);

    // s0: Q path
    cudaStreamWaitEvent(0, eW, 0);
    rmsnorm_round<<<TOK, 256>>>(qc, QKVD, q_norm_w, q1n, QLORA, QLORA);
    mma_gemm<<<dim3((NH*DQK)/128, TOK/128), 128, SMEMF>>>(
        q1n, wqu, q,
        QLORA, 0, QLORA, 0, NH*DQK, 0, 0, 1,
        TOK, NH*DQK, QLORA, 1.f, 0, 0);

    cudaStreamWaitEvent(0, eKv, 0);
    rope_pack<<<BHN*SEQ, 256>>>();

    // scores
    mma_gemm<<<dim3(SEQ/128, SEQ/128, BHN), 128, SMEMF>>>(
        qb, kb, attn_out,
        DQK, (long)SEQ*DQK, DQK, (long)SEQ*DQK,
        SEQ, (long)SEQ*SEQ, 0, 1,
        SEQ, SEQ, DQK, qk_scale, 1, 0);

    softmax_causal<<<BHN*SEQ, 256>>>(attn_out);

    cudaStreamWaitEvent(0, eVt, 0);
    mma_gemm<<<dim3(DV/128, SEQ/128, BHN), 128, SMEMF>>>(
        attn_out, vt, om,
        SEQ, (long)SEQ*SEQ, SEQ, (long)DV*SEQ,
        NH*DV, (long)SEQ*NH*DV, DV, NH,
        SEQ, DV, SEQ, 1.f, 2, 1);

    // out = om @ w_out^T
    mma_gemm<<<dim3(HID/128, TOK/128), 128, SMEMF>>>(
        om, wo, out_final,
        NH*DV, 0, NH*DV, 0, HID, 0, 0, 1,
        TOK, HID, NH*DV, 1.f, 0, 0);
}